// round 8
// baseline (speedup 1.0000x reference)
#include <cuda_runtime.h>

// AlignBlock on sm_103a, round 8: crossbar-roofline fixes.
// Model: smem crossbar 128B/cyc/SM vs 64 FMA-lanes/cyc -> 2 B/FMA budget.
//  - chanmix: r1 shape (AT the FFMA floor), merged Q+K, 2048 blocks
//  - corr: conflict-free transpose fills + 4t x 8d tiles (2 B/FMA), t-tile 128
//  - conv+softmax: unchanged (~3.5us)
//  - align: 4t x 8f tiles (1.5 B/FMA), rolling X window
// Shapes: B=2, C=H=64, T=512, F=64, DMAX=32. All fp32.

#define Bn 2
#define Cn 64
#define Hn 64
#define Tn 512
#define Fn 64
#define Dn 32

__device__ float g_Q[Bn * Hn * Tn * Fn];
__device__ float g_K[Bn * Hn * Tn * Fn];
__device__ float g_V[Bn * Hn * Tn * Dn];
__device__ float g_A[Bn * Tn * Dn];

// ---------------------------------------------------------------------------
// Kernel 1: channel mix for Q AND K (merged; r1 inner shape = at FMA floor).
// out[b,h,t,f] = sum_c w[h,c] * x[b,c,t,f] + bias[h]
// grid = 2*B*T = 2048 blocks, 256 threads.
// ---------------------------------------------------------------------------
__global__ void __launch_bounds__(256) k_chanmix(const float* __restrict__ xm,
                                                 const float* __restrict__ wm,
                                                 const float* __restrict__ bm,
                                                 const float* __restrict__ xr,
                                                 const float* __restrict__ wr,
                                                 const float* __restrict__ br) {
    const int tid = threadIdx.x;
    const int which = blockIdx.x >> 10;
    const int rem = blockIdx.x & 1023;
    const int b = rem >> 9;
    const int t = rem & 511;

    const float* x    = which ? xr : xm;
    const float* w    = which ? wr : wm;
    const float* bias = which ? br : bm;
    float* out        = which ? g_K : g_Q;

    __shared__ float xs[64][68];        // [c][f]
    __shared__ float wst[64][68];       // [c][h]

#pragma unroll
    for (int it = 0; it < 16; it++) {
        int idx = tid + it * 256;
        int r = idx >> 6, q = idx & 63;
        xs[r][q] = x[((b * 64 + r) * 512 + t) * 64 + q];
        wst[q][r] = w[idx];
    }
    __syncthreads();

    const int f0 = (tid & 15) * 4;
    const int h0 = (tid >> 4) * 4;

    float4 acc[4];
#pragma unroll
    for (int a = 0; a < 4; a++) acc[a] = make_float4(0.f, 0.f, 0.f, 0.f);

#pragma unroll 8
    for (int c = 0; c < 64; c++) {
        float4 xv = *(const float4*)&xs[c][f0];
        float4 wv = *(const float4*)&wst[c][h0];
        acc[0].x += wv.x * xv.x; acc[0].y += wv.x * xv.y;
        acc[0].z += wv.x * xv.z; acc[0].w += wv.x * xv.w;
        acc[1].x += wv.y * xv.x; acc[1].y += wv.y * xv.y;
        acc[1].z += wv.y * xv.z; acc[1].w += wv.y * xv.w;
        acc[2].x += wv.z * xv.x; acc[2].y += wv.z * xv.y;
        acc[2].z += wv.z * xv.z; acc[2].w += wv.z * xv.w;
        acc[3].x += wv.w * xv.x; acc[3].y += wv.w * xv.y;
        acc[3].z += wv.w * xv.z; acc[3].w += wv.w * xv.w;
    }

#pragma unroll
    for (int a = 0; a < 4; a++) {
        float bb = __ldg(&bias[h0 + a]);
        float4 r = acc[a];
        r.x += bb; r.y += bb; r.z += bb; r.w += bb;
        *(float4*)&out[((b * 64 + h0 + a) * 512 + t) * 64 + f0] = r;
    }
}

// ---------------------------------------------------------------------------
// Kernel 2: banded correlation. Conflict-free transpose fills + 4t x 8d.
// V[b,h,t,d] = (1/8) * sum_f Q[b,h,t,f] * K[b,h,t-31+d,f]
// grid = B*H*(T/128) = 512 blocks, 128 threads, 74KB dynamic smem.
// Fill STS addresses vary with LANE along the padded-row dim -> 0 conflicts.
// Compute: Q 16B + K 48B per 32 FMAs = 2 B/FMA (crossbar == FMA floor).
// ---------------------------------------------------------------------------
#define QROW 132            // Qs row stride (floats), 16B-aligned
#define KROW 164            // Ks row stride
#define CORR_SMEM ((64 * QROW + 64 * KROW) * 4)   // 75776 bytes

__global__ void __launch_bounds__(128) k_corr() {
    extern __shared__ float cs[];
    float* Qs = cs;                 // [f][i], i = 0..127
    float* Ks = cs + 64 * QROW;     // [f][r], r = t_global-(t0-31), 0..158

    const int tid = threadIdx.x;
    const int warp = tid >> 5, lane = tid & 31;
    const int t0 = (blockIdx.x & 3) * 128;
    const int h  = (blockIdx.x >> 2) & 63;
    const int b  = blockIdx.x >> 8;

    const float* qg = g_Q + ((b * 64 + h) * 512 + t0) * 64;
    const float* kg = g_K + ((b * 64 + h) * 512) * 64;

    // Q fill: 128 i x 16 fq. Warp handles fq = warp*4+it; lanes sweep i.
#pragma unroll
    for (int it = 0; it < 4; it++) {
        int fq = warp * 4 + it;
#pragma unroll
        for (int sub = 0; sub < 4; sub++) {
            int i = lane + sub * 32;
            float4 v = *(const float4*)&qg[i * 64 + fq * 4];
            Qs[(4 * fq + 0) * QROW + i] = v.x;
            Qs[(4 * fq + 1) * QROW + i] = v.y;
            Qs[(4 * fq + 2) * QROW + i] = v.z;
            Qs[(4 * fq + 3) * QROW + i] = v.w;
        }
    }
    // K fill: r = 0..158 (t = t0-31+r).
#pragma unroll
    for (int it = 0; it < 4; it++) {
        int fq = warp * 4 + it;
#pragma unroll
        for (int sub = 0; sub < 5; sub++) {
            int r = lane + sub * 32;
            if (r < 159) {
                int tr = t0 - 31 + r;
                float4 v = make_float4(0.f, 0.f, 0.f, 0.f);
                if (tr >= 0) v = *(const float4*)&kg[tr * 64 + fq * 4];
                Ks[(4 * fq + 0) * KROW + r] = v.x;
                Ks[(4 * fq + 1) * KROW + r] = v.y;
                Ks[(4 * fq + 2) * KROW + r] = v.z;
                Ks[(4 * fq + 3) * KROW + r] = v.w;
            }
        }
    }
    __syncthreads();

    const int d0 = (tid & 3) * 8;    // 0,8,16,24
    const int i0 = (tid >> 2) * 4;   // 0..124
    const int r0 = i0 + d0;          // K base row

    float acc[4][8];
#pragma unroll
    for (int a = 0; a < 4; a++)
#pragma unroll
        for (int e = 0; e < 8; e++) acc[a][e] = 0.f;

#pragma unroll 4
    for (int f = 0; f < 64; f++) {
        const float* qrow = Qs + f * QROW;
        const float* krow = Ks + f * KROW;
        float4 q4 = *(const float4*)&qrow[i0];
        float4 k0 = *(const float4*)&krow[r0];
        float4 k1 = *(const float4*)&krow[r0 + 4];
        float4 k2 = *(const float4*)&krow[r0 + 8];
        float qq[4] = {q4.x, q4.y, q4.z, q4.w};
        float kk[12] = {k0.x, k0.y, k0.z, k0.w, k1.x, k1.y, k1.z, k1.w,
                        k2.x, k2.y, k2.z, k2.w};
#pragma unroll
        for (int a = 0; a < 4; a++)
#pragma unroll
            for (int e = 0; e < 8; e++)
                acc[a][e] += qq[a] * kk[a + e];   // K row = r0 + a + e
    }

    float* vg = g_V + ((b * 64 + h) * 512 + t0) * 32;
#pragma unroll
    for (int a = 0; a < 4; a++) {
        float4 r0v = make_float4(acc[a][0] * 0.125f, acc[a][1] * 0.125f,
                                 acc[a][2] * 0.125f, acc[a][3] * 0.125f);
        float4 r1v = make_float4(acc[a][4] * 0.125f, acc[a][5] * 0.125f,
                                 acc[a][6] * 0.125f, acc[a][7] * 0.125f);
        *(float4*)&vg[(i0 + a) * 32 + d0] = r0v;
        *(float4*)&vg[(i0 + a) * 32 + d0 + 4] = r1v;
    }
}

// ---------------------------------------------------------------------------
// Kernel 3: (5,3) conv over (T,dmax) reducing H->1, + softmax over dmax.
// (conv bias dropped: uniform shift is softmax-invariant)
// grid = B*(T/8) = 128 blocks, 128 threads.
// ---------------------------------------------------------------------------
__global__ void __launch_bounds__(128) k_convsoftmax(const float* __restrict__ wconv) {
    const int tid = threadIdx.x;
    const int b  = blockIdx.x >> 6;
    const int t0 = (blockIdx.x & 63) * 8;

    __shared__ float Vs[16][12][34];
    __shared__ float wcs[64][16];
    __shared__ float red[8][33];

    for (int idx = tid; idx < 960; idx += 128)
        wcs[idx / 15][idx % 15] = wconv[idx];
    for (int idx = tid; idx < 16 * 12; idx += 128) {
        Vs[idx / 12][idx % 12][0]  = 0.0f;
        Vs[idx / 12][idx % 12][33] = 0.0f;
    }

    const int tl = tid >> 4;
    const int d  = (tid & 15) * 2;

    float accA0 = 0.f, accA1 = 0.f, accB0 = 0.f, accB1 = 0.f;

    for (int hc = 0; hc < 4; hc++) {
        __syncthreads();
        for (int g = tid; g < 1536; g += 128) {
            int dq = g & 7;
            int hr = g >> 3;
            int r  = hr % 12;
            int hl = hr / 12;
            int tt = t0 - 4 + r;
            float4 v = make_float4(0.f, 0.f, 0.f, 0.f);
            if (tt >= 0)
                v = *(const float4*)&g_V[((b * 64 + hc * 16 + hl) * 512 + tt) * 32 + dq * 4];
            Vs[hl][r][1 + dq * 4 + 0] = v.x;
            Vs[hl][r][1 + dq * 4 + 1] = v.y;
            Vs[hl][r][1 + dq * 4 + 2] = v.z;
            Vs[hl][r][1 + dq * 4 + 3] = v.w;
        }
        __syncthreads();

#pragma unroll 2
        for (int hl = 0; hl < 16; hl++) {
            int hh = hc * 16 + hl;
            float wreg[16];
#pragma unroll
            for (int k4 = 0; k4 < 4; k4++) {
                float4 wv = *(const float4*)&wcs[hh][k4 * 4];
                wreg[k4 * 4 + 0] = wv.x; wreg[k4 * 4 + 1] = wv.y;
                wreg[k4 * 4 + 2] = wv.z; wreg[k4 * 4 + 3] = wv.w;
            }
#pragma unroll
            for (int i = 0; i < 5; i++) {
                float2 u = *(const float2*)&Vs[hl][tl + i][d];
                float2 v = *(const float2*)&Vs[hl][tl + i][d + 2];
                float w0 = wreg[i * 3], w1 = wreg[i * 3 + 1], w2 = wreg[i * 3 + 2];
                if (i & 1) {
                    accB0 += u.x * w0 + u.y * w1 + v.x * w2;
                    accB1 += u.y * w0 + v.x * w1 + v.y * w2;
                } else {
                    accA0 += u.x * w0 + u.y * w1 + v.x * w2;
                    accA1 += u.y * w0 + v.x * w1 + v.y * w2;
                }
            }
        }
    }

    red[tl][d]     = accA0 + accB0;
    red[tl][d + 1] = accA1 + accB1;
    __syncthreads();

    const int wd = tid >> 5, lane = tid & 31;
#pragma unroll
    for (int rr = 0; rr < 2; rr++) {
        int row = wd * 2 + rr;
        float v = red[row][lane];
        float mx = v;
#pragma unroll
        for (int o = 16; o > 0; o >>= 1)
            mx = fmaxf(mx, __shfl_xor_sync(0xffffffffu, mx, o));
        float e = __expf(v - mx);
        float s = e;
#pragma unroll
        for (int o = 16; o > 0; o >>= 1)
            s += __shfl_xor_sync(0xffffffffu, s, o);
        g_A[(b * 512 + t0 + row) * 32 + lane] = e / s;
    }
}

// ---------------------------------------------------------------------------
// Kernel 4: aligned[b,c,t,f] = sum_d A[b,t,d] * x_ref[b,c,t-31+d,f]
// grid = B*C*(T/64) = 1024 blocks, 128 threads. Thread tile: 4t x 8f,
// rolling 7-row X register window. A 0.5 + X 1.0 = 1.5 B/FMA.
// ---------------------------------------------------------------------------
__global__ void __launch_bounds__(128) k_align(const float* __restrict__ xref,
                                               float* __restrict__ out) {
    const int tid = threadIdx.x;
    const int t0 = (blockIdx.x & 7) * 64;
    const int c  = (blockIdx.x >> 3) & 63;
    const int b  = blockIdx.x >> 9;

    __shared__ float As[64][36];    // [i][d]
    __shared__ float Xs[95][68];    // [r][f], r = t_global-(t0-31), 0..94

    const float* ag = g_A + (b * 512 + t0) * 32;
    const float* xg = xref + ((b * 64 + c) * 512) * 64;

    for (int idx = tid; idx < 64 * 8; idx += 128) {           // A: 512 quads
        int i = idx >> 3, dq = idx & 7;
        *(float4*)&As[i][dq * 4] = *(const float4*)&ag[i * 32 + dq * 4];
    }
    for (int idx = tid; idx < 95 * 16; idx += 128) {          // X: 1520 quads
        int r = idx >> 4, fq = idx & 15;
        int tr = t0 - 31 + r;
        float4 v = make_float4(0.f, 0.f, 0.f, 0.f);
        if (tr >= 0) v = *(const float4*)&xg[tr * 64 + fq * 4];
        *(float4*)&Xs[r][fq * 4] = v;
    }
    __syncthreads();

    const int f0 = (tid & 7) * 8;    // 0..56
    const int i0 = (tid >> 3) * 4;   // 0..60

    float4 acc[4][2];
#pragma unroll
    for (int a = 0; a < 4; a++) {
        acc[a][0] = make_float4(0.f, 0.f, 0.f, 0.f);
        acc[a][1] = make_float4(0.f, 0.f, 0.f, 0.f);
    }

    float4 xv[7][2];
#pragma unroll
    for (int k = 0; k < 7; k++) {
        xv[k][0] = *(const float4*)&Xs[i0 + k][f0];
        xv[k][1] = *(const float4*)&Xs[i0 + k][f0 + 4];
    }

#pragma unroll
    for (int d0 = 0; d0 < 32; d0 += 4) {
        float4 av[4];
#pragma unroll
        for (int a = 0; a < 4; a++) av[a] = *(const float4*)&As[i0 + a][d0];
#pragma unroll
        for (int a = 0; a < 4; a++) {
            float aa[4] = {av[a].x, av[a].y, av[a].z, av[a].w};
#pragma unroll
            for (int dd = 0; dd < 4; dd++) {
                float4 x0 = xv[a + dd][0];
                float4 x1 = xv[a + dd][1];
                acc[a][0].x += aa[dd] * x0.x;
                acc[a][0].y += aa[dd] * x0.y;
                acc[a][0].z += aa[dd] * x0.z;
                acc[a][0].w += aa[dd] * x0.w;
                acc[a][1].x += aa[dd] * x1.x;
                acc[a][1].y += aa[dd] * x1.y;
                acc[a][1].z += aa[dd] * x1.z;
                acc[a][1].w += aa[dd] * x1.w;
            }
        }
        if (d0 < 28) {
#pragma unroll
            for (int k = 0; k < 3; k++) {
                xv[k][0] = xv[k + 4][0];
                xv[k][1] = xv[k + 4][1];
            }
#pragma unroll
            for (int k = 3; k < 7; k++) {
                xv[k][0] = *(const float4*)&Xs[i0 + d0 + 4 + k][f0];
                xv[k][1] = *(const float4*)&Xs[i0 + d0 + 4 + k][f0 + 4];
            }
        }
    }

    float* og = out + ((b * 64 + c) * 512 + t0) * 64;
#pragma unroll
    for (int a = 0; a < 4; a++) {
        *(float4*)&og[(i0 + a) * 64 + f0] = acc[a][0];
        *(float4*)&og[(i0 + a) * 64 + f0 + 4] = acc[a][1];
    }
}

// ---------------------------------------------------------------------------
extern "C" void kernel_launch(void* const* d_in, const int* in_sizes, int n_in,
                              void* d_out, int out_size) {
    (void)in_sizes; (void)n_in; (void)out_size;
    const float* x_mic  = (const float*)d_in[0];
    const float* x_ref  = (const float*)d_in[1];
    const float* w_mic  = (const float*)d_in[2];
    const float* b_mic  = (const float*)d_in[3];
    const float* w_ref  = (const float*)d_in[4];
    const float* b_ref  = (const float*)d_in[5];
    const float* w_conv = (const float*)d_in[6];
    float* out = (float*)d_out;

    cudaFuncSetAttribute(k_corr, cudaFuncAttributeMaxDynamicSharedMemorySize,
                         CORR_SMEM);

    k_chanmix<<<2 * Bn * Tn, 256>>>(x_mic, w_mic, b_mic, x_ref, w_ref, b_ref);
    k_corr<<<Bn * Hn * (Tn / 128), 128, CORR_SMEM>>>();
    k_convsoftmax<<<Bn * (Tn / 8), 128>>>(w_conv);
    k_align<<<Bn * Cn * (Tn / 64), 128>>>(x_ref, out);
}

// round 9
// speedup vs baseline: 1.1371x; 1.1371x over previous
#include <cuda_runtime.h>

// AlignBlock on sm_103a, round 9: best-measured assembly + one bounded change
// (conflict-free transpose fills in corr; everything else proven pieces).
//  - chanmix: r1 shape (at scalar-FMA floor), merged Q+K, 2048 blocks
//  - corr: r1 compute (4t x 4d, transposed smem) + lane-contiguous fills
//  - conv+softmax: r2 rewrite (~3.5us)
//  - align: r6 version (t-tile 32, 128 thr, 56 regs, measured 17.6us)
// Shapes: B=2, C=H=64, T=512, F=64, DMAX=32. All fp32.

#define Bn 2
#define Cn 64
#define Hn 64
#define Tn 512
#define Fn 64
#define Dn 32

__device__ float g_Q[Bn * Hn * Tn * Fn];
__device__ float g_K[Bn * Hn * Tn * Fn];
__device__ float g_V[Bn * Hn * Tn * Dn];
__device__ float g_A[Bn * Tn * Dn];

// ---------------------------------------------------------------------------
// Kernel 1: channel mix for Q AND K (merged).
// out[b,h,t,f] = sum_c w[h,c] * x[b,c,t,f] + bias[h]
// grid = 2*B*T = 2048 blocks, 256 threads. Thread tile 4h x 4f (r1 shape).
// ---------------------------------------------------------------------------
__global__ void __launch_bounds__(256) k_chanmix(const float* __restrict__ xm,
                                                 const float* __restrict__ wm,
                                                 const float* __restrict__ bm,
                                                 const float* __restrict__ xr,
                                                 const float* __restrict__ wr,
                                                 const float* __restrict__ br) {
    const int tid = threadIdx.x;
    const int which = blockIdx.x >> 10;
    const int rem = blockIdx.x & 1023;
    const int b = rem >> 9;
    const int t = rem & 511;

    const float* x    = which ? xr : xm;
    const float* w    = which ? wr : wm;
    const float* bias = which ? br : bm;
    float* out        = which ? g_K : g_Q;

    __shared__ float xs[64][68];        // [c][f]
    __shared__ float wst[64][68];       // [c][h]

#pragma unroll
    for (int it = 0; it < 16; it++) {
        int idx = tid + it * 256;
        int r = idx >> 6, q = idx & 63;
        xs[r][q] = x[((b * 64 + r) * 512 + t) * 64 + q];
        wst[q][r] = w[idx];
    }
    __syncthreads();

    const int f0 = (tid & 15) * 4;
    const int h0 = (tid >> 4) * 4;

    float4 acc[4];
#pragma unroll
    for (int a = 0; a < 4; a++) acc[a] = make_float4(0.f, 0.f, 0.f, 0.f);

#pragma unroll 8
    for (int c = 0; c < 64; c++) {
        float4 xv = *(const float4*)&xs[c][f0];
        float4 wv = *(const float4*)&wst[c][h0];
        acc[0].x += wv.x * xv.x; acc[0].y += wv.x * xv.y;
        acc[0].z += wv.x * xv.z; acc[0].w += wv.x * xv.w;
        acc[1].x += wv.y * xv.x; acc[1].y += wv.y * xv.y;
        acc[1].z += wv.y * xv.z; acc[1].w += wv.y * xv.w;
        acc[2].x += wv.z * xv.x; acc[2].y += wv.z * xv.y;
        acc[2].z += wv.z * xv.z; acc[2].w += wv.z * xv.w;
        acc[3].x += wv.w * xv.x; acc[3].y += wv.w * xv.y;
        acc[3].z += wv.w * xv.z; acc[3].w += wv.w * xv.w;
    }

#pragma unroll
    for (int a = 0; a < 4; a++) {
        float bb = __ldg(&bias[h0 + a]);
        float4 r = acc[a];
        r.x += bb; r.y += bb; r.z += bb; r.w += bb;
        *(float4*)&out[((b * 64 + h0 + a) * 512 + t) * 64 + f0] = r;
    }
}

// ---------------------------------------------------------------------------
// Kernel 2: banded correlation. r1 compute shape; conflict-free fills.
// V[b,h,t,d] = (1/8) * sum_f Q[b,h,t,f] * K[b,h,t-31+d,f]
// grid = B*H*(T/64) = 1024 blocks, 128 threads. Thread tile 4t x 4d.
// Fills: warp handles fq = warp*4+it; lanes sweep the contiguous i/r dim
// -> every STS hits stride-1 banks (zero conflicts). LDG remains coalesced.
// ---------------------------------------------------------------------------
__global__ void __launch_bounds__(128) k_corr() {
    const int tid = threadIdx.x;
    const int warp = tid >> 5, lane = tid & 31;
    const int t0 = (blockIdx.x & 7) * 64;
    const int h  = (blockIdx.x >> 3) & 63;
    const int b  = blockIdx.x >> 9;

    __shared__ float Qs[64][68];    // [f][i], i = 0..63
    __shared__ float Ks[64][100];   // [f][r], r = t_global-(t0-31), 0..94

    const float* qg = g_Q + ((b * 64 + h) * 512 + t0) * 64;
    const float* kg = g_K + ((b * 64 + h) * 512) * 64;

    // Q fill: 64 i x 16 fq quads. warp -> fq group, lanes sweep i.
#pragma unroll
    for (int it = 0; it < 4; it++) {
        int fq = warp * 4 + it;
#pragma unroll
        for (int sub = 0; sub < 2; sub++) {
            int i = lane + sub * 32;
            float4 v = *(const float4*)&qg[i * 64 + fq * 4];
            Qs[4 * fq + 0][i] = v.x;
            Qs[4 * fq + 1][i] = v.y;
            Qs[4 * fq + 2][i] = v.z;
            Qs[4 * fq + 3][i] = v.w;
        }
    }
    // K fill: r = 0..94 (t = t0-31+r).
#pragma unroll
    for (int it = 0; it < 4; it++) {
        int fq = warp * 4 + it;
#pragma unroll
        for (int sub = 0; sub < 3; sub++) {
            int r = lane + sub * 32;
            if (r < 95) {
                int tr = t0 - 31 + r;
                float4 v = make_float4(0.f, 0.f, 0.f, 0.f);
                if (tr >= 0) v = *(const float4*)&kg[tr * 64 + fq * 4];
                Ks[4 * fq + 0][r] = v.x;
                Ks[4 * fq + 1][r] = v.y;
                Ks[4 * fq + 2][r] = v.z;
                Ks[4 * fq + 3][r] = v.w;
            }
        }
    }
    __syncthreads();

    const int d0 = (tid & 7) * 4;
    const int i0 = (tid >> 3) * 4;

    float acc[4][4];
#pragma unroll
    for (int a = 0; a < 4; a++)
#pragma unroll
        for (int e = 0; e < 4; e++) acc[a][e] = 0.f;

#pragma unroll 8
    for (int f = 0; f < 64; f++) {
        float4 q4 = *(const float4*)&Qs[f][i0];
        float4 k0 = *(const float4*)&Ks[f][i0 + d0];
        float4 k1 = *(const float4*)&Ks[f][i0 + d0 + 4];
        float qq[4] = {q4.x, q4.y, q4.z, q4.w};
        float kk[8] = {k0.x, k0.y, k0.z, k0.w, k1.x, k1.y, k1.z, k1.w};
#pragma unroll
        for (int a = 0; a < 4; a++)
#pragma unroll
            for (int e = 0; e < 4; e++)
                acc[a][e] += qq[a] * kk[a + e];
    }

    float* vg = g_V + ((b * 64 + h) * 512 + t0) * 32;
#pragma unroll
    for (int a = 0; a < 4; a++) {
        float4 r = make_float4(acc[a][0] * 0.125f, acc[a][1] * 0.125f,
                               acc[a][2] * 0.125f, acc[a][3] * 0.125f);
        *(float4*)&vg[(i0 + a) * 32 + d0] = r;
    }
}

// ---------------------------------------------------------------------------
// Kernel 3: (5,3) conv over (T,dmax) reducing H->1, + softmax over dmax.
// (conv bias dropped: uniform shift is softmax-invariant)
// grid = B*(T/8) = 128 blocks, 128 threads.
// ---------------------------------------------------------------------------
__global__ void __launch_bounds__(128) k_convsoftmax(const float* __restrict__ wconv) {
    const int tid = threadIdx.x;
    const int b  = blockIdx.x >> 6;
    const int t0 = (blockIdx.x & 63) * 8;

    __shared__ float Vs[16][12][34];
    __shared__ float wcs[64][16];
    __shared__ float red[8][33];

    for (int idx = tid; idx < 960; idx += 128)
        wcs[idx / 15][idx % 15] = wconv[idx];
    for (int idx = tid; idx < 16 * 12; idx += 128) {
        Vs[idx / 12][idx % 12][0]  = 0.0f;
        Vs[idx / 12][idx % 12][33] = 0.0f;
    }

    const int tl = tid >> 4;
    const int d  = (tid & 15) * 2;

    float accA0 = 0.f, accA1 = 0.f, accB0 = 0.f, accB1 = 0.f;

    for (int hc = 0; hc < 4; hc++) {
        __syncthreads();
        for (int g = tid; g < 1536; g += 128) {
            int dq = g & 7;
            int hr = g >> 3;
            int r  = hr % 12;
            int hl = hr / 12;
            int tt = t0 - 4 + r;
            float4 v = make_float4(0.f, 0.f, 0.f, 0.f);
            if (tt >= 0)
                v = *(const float4*)&g_V[((b * 64 + hc * 16 + hl) * 512 + tt) * 32 + dq * 4];
            Vs[hl][r][1 + dq * 4 + 0] = v.x;
            Vs[hl][r][1 + dq * 4 + 1] = v.y;
            Vs[hl][r][1 + dq * 4 + 2] = v.z;
            Vs[hl][r][1 + dq * 4 + 3] = v.w;
        }
        __syncthreads();

#pragma unroll 2
        for (int hl = 0; hl < 16; hl++) {
            int hh = hc * 16 + hl;
            float wreg[16];
#pragma unroll
            for (int k4 = 0; k4 < 4; k4++) {
                float4 wv = *(const float4*)&wcs[hh][k4 * 4];
                wreg[k4 * 4 + 0] = wv.x; wreg[k4 * 4 + 1] = wv.y;
                wreg[k4 * 4 + 2] = wv.z; wreg[k4 * 4 + 3] = wv.w;
            }
#pragma unroll
            for (int i = 0; i < 5; i++) {
                float2 u = *(const float2*)&Vs[hl][tl + i][d];
                float2 v = *(const float2*)&Vs[hl][tl + i][d + 2];
                float w0 = wreg[i * 3], w1 = wreg[i * 3 + 1], w2 = wreg[i * 3 + 2];
                if (i & 1) {
                    accB0 += u.x * w0 + u.y * w1 + v.x * w2;
                    accB1 += u.y * w0 + v.x * w1 + v.y * w2;
                } else {
                    accA0 += u.x * w0 + u.y * w1 + v.x * w2;
                    accA1 += u.y * w0 + v.x * w1 + v.y * w2;
                }
            }
        }
    }

    red[tl][d]     = accA0 + accB0;
    red[tl][d + 1] = accA1 + accB1;
    __syncthreads();

    const int wd = tid >> 5, lane = tid & 31;
#pragma unroll
    for (int rr = 0; rr < 2; rr++) {
        int row = wd * 2 + rr;
        float v = red[row][lane];
        float mx = v;
#pragma unroll
        for (int o = 16; o > 0; o >>= 1)
            mx = fmaxf(mx, __shfl_xor_sync(0xffffffffu, mx, o));
        float e = __expf(v - mx);
        float s = e;
#pragma unroll
        for (int o = 16; o > 0; o >>= 1)
            s += __shfl_xor_sync(0xffffffffu, s, o);
        g_A[(b * 512 + t0 + row) * 32 + lane] = e / s;
    }
}

// ---------------------------------------------------------------------------
// Kernel 4: aligned[b,c,t,f] = sum_d A[b,t,d] * x_ref[b,c,t-31+d,f]
// grid = B*C*(T/32) = 2048 blocks, 128 threads. Thread tile: 4t x 4f,
// rolling 7-row X register window. (r6 version, measured 17.6us)
// ---------------------------------------------------------------------------
__global__ void __launch_bounds__(128) k_align(const float* __restrict__ xref,
                                               float* __restrict__ out) {
    const int tid = threadIdx.x;
    const int t0 = (blockIdx.x & 15) * 32;
    const int c  = (blockIdx.x >> 4) & 63;
    const int b  = blockIdx.x >> 10;

    __shared__ float As[32][36];    // [i][d]
    __shared__ float Xs[63][68];    // [r][f], r = t_global-(t0-31), 0..62

    const float* ag = g_A + (b * 512 + t0) * 32;
    const float* xg = xref + ((b * 64 + c) * 512) * 64;

    for (int idx = tid; idx < 32 * 8; idx += 128) {
        int i = idx >> 3, dq = idx & 7;
        *(float4*)&As[i][dq * 4] = *(const float4*)&ag[i * 32 + dq * 4];
    }
    for (int idx = tid; idx < 63 * 16; idx += 128) {
        int r = idx >> 4, fq = idx & 15;
        int tr = t0 - 31 + r;
        float4 v = make_float4(0.f, 0.f, 0.f, 0.f);
        if (tr >= 0) v = *(const float4*)&xg[tr * 64 + fq * 4];
        *(float4*)&Xs[r][fq * 4] = v;
    }
    __syncthreads();

    const int f0 = (tid & 15) * 4;
    const int i0 = (tid >> 4) * 4;

    float4 acc[4];
#pragma unroll
    for (int a = 0; a < 4; a++) acc[a] = make_float4(0.f, 0.f, 0.f, 0.f);

    float4 xv[7];
#pragma unroll
    for (int k = 0; k < 7; k++)
        xv[k] = *(const float4*)&Xs[i0 + k][f0];

#pragma unroll
    for (int d0 = 0; d0 < 32; d0 += 4) {
        float4 av[4];
#pragma unroll
        for (int a = 0; a < 4; a++) av[a] = *(const float4*)&As[i0 + a][d0];
#pragma unroll
        for (int a = 0; a < 4; a++) {
            float aa[4] = {av[a].x, av[a].y, av[a].z, av[a].w};
#pragma unroll
            for (int dd = 0; dd < 4; dd++) {
                float4 x4 = xv[a + dd];
                acc[a].x += aa[dd] * x4.x;
                acc[a].y += aa[dd] * x4.y;
                acc[a].z += aa[dd] * x4.z;
                acc[a].w += aa[dd] * x4.w;
            }
        }
        if (d0 < 28) {
            xv[0] = xv[4]; xv[1] = xv[5]; xv[2] = xv[6];
#pragma unroll
            for (int k = 3; k < 7; k++)
                xv[k] = *(const float4*)&Xs[i0 + d0 + 4 + k][f0];
        }
    }

    float* og = out + ((b * 64 + c) * 512 + t0) * 64;
#pragma unroll
    for (int a = 0; a < 4; a++)
        *(float4*)&og[(i0 + a) * 64 + f0] = acc[a];
}

// ---------------------------------------------------------------------------
extern "C" void kernel_launch(void* const* d_in, const int* in_sizes, int n_in,
                              void* d_out, int out_size) {
    (void)in_sizes; (void)n_in; (void)out_size;
    const float* x_mic  = (const float*)d_in[0];
    const float* x_ref  = (const float*)d_in[1];
    const float* w_mic  = (const float*)d_in[2];
    const float* b_mic  = (const float*)d_in[3];
    const float* w_ref  = (const float*)d_in[4];
    const float* b_ref  = (const float*)d_in[5];
    const float* w_conv = (const float*)d_in[6];
    float* out = (float*)d_out;

    k_chanmix<<<2 * Bn * Tn, 256>>>(x_mic, w_mic, b_mic, x_ref, w_ref, b_ref);
    k_corr<<<Bn * Hn * (Tn / 64), 128>>>();
    k_convsoftmax<<<Bn * (Tn / 8), 128>>>(w_conv);
    k_align<<<Bn * Cn * (Tn / 32), 128>>>(x_ref, out);
}

// round 10
// speedup vs baseline: 1.1692x; 1.0282x over previous
#include <cuda_runtime.h>

// AlignBlock on sm_103a, round 10: instruction-diet on the r9 winner (84.0us).
//  - chanmix: natural-layout weights (no transpose STS conflicts), float4 fills
//  - corr: unchanged from r9 (conflict-free fills + 4t x 4d)
//  - conv+softmax: unchanged
//  - align: rolling window removed (12 MOVs/step -> 0), direct X loads
// Shapes: B=2, C=H=64, T=512, F=64, DMAX=32. All fp32.

#define Bn 2
#define Cn 64
#define Hn 64
#define Tn 512
#define Fn 64
#define Dn 32

__device__ float g_Q[Bn * Hn * Tn * Fn];
__device__ float g_K[Bn * Hn * Tn * Fn];
__device__ float g_V[Bn * Hn * Tn * Dn];
__device__ float g_A[Bn * Tn * Dn];

// ---------------------------------------------------------------------------
// Kernel 1: channel mix for Q AND K (merged).
// out[b,h,t,f] = sum_c w[h,c] * x[b,c,t,f] + bias[h]
// grid = 2*B*T = 2048 blocks, 256 threads. Thread tile 4h x 4f.
// Weights kept NATURAL [h][c]: coalesced LDG.128 -> stride-1 STS.128 fills;
// compute reads 4 weight scalars per c (2 distinct h-groups/warp = broadcast).
// ---------------------------------------------------------------------------
__global__ void __launch_bounds__(256) k_chanmix(const float* __restrict__ xm,
                                                 const float* __restrict__ wm,
                                                 const float* __restrict__ bm,
                                                 const float* __restrict__ xr,
                                                 const float* __restrict__ wr,
                                                 const float* __restrict__ br) {
    const int tid = threadIdx.x;
    const int which = blockIdx.x >> 10;
    const int rem = blockIdx.x & 1023;
    const int b = rem >> 9;
    const int t = rem & 511;

    const float* x    = which ? xr : xm;
    const float* w    = which ? wr : wm;
    const float* bias = which ? br : bm;
    float* out        = which ? g_K : g_Q;

    __shared__ float xs[64][68];        // [c][f]
    __shared__ float ws[64][68];        // [h][c]  (natural)

    // fills: 1024 + 1024 float4 over 256 threads = 8 iters
#pragma unroll
    for (int it = 0; it < 4; it++) {
        int idx = tid + it * 256;               // 0..1023
        int q4 = (idx & 15) * 4;
        int r  = idx >> 4;
        *(float4*)&xs[r][q4] =
            *(const float4*)&x[((b * 64 + r) * 512 + t) * 64 + q4];
        *(float4*)&ws[r][q4] = *(const float4*)&w[r * 64 + q4];
    }
    __syncthreads();

    const int f0 = (tid & 15) * 4;
    const int h0 = (tid >> 4) * 4;

    float4 acc[4];
#pragma unroll
    for (int a = 0; a < 4; a++) acc[a] = make_float4(0.f, 0.f, 0.f, 0.f);

#pragma unroll 8
    for (int c = 0; c < 64; c++) {
        float4 xv = *(const float4*)&xs[c][f0];
        float w0 = ws[h0 + 0][c];
        float w1 = ws[h0 + 1][c];
        float w2 = ws[h0 + 2][c];
        float w3 = ws[h0 + 3][c];
        acc[0].x += w0 * xv.x; acc[0].y += w0 * xv.y;
        acc[0].z += w0 * xv.z; acc[0].w += w0 * xv.w;
        acc[1].x += w1 * xv.x; acc[1].y += w1 * xv.y;
        acc[1].z += w1 * xv.z; acc[1].w += w1 * xv.w;
        acc[2].x += w2 * xv.x; acc[2].y += w2 * xv.y;
        acc[2].z += w2 * xv.z; acc[2].w += w2 * xv.w;
        acc[3].x += w3 * xv.x; acc[3].y += w3 * xv.y;
        acc[3].z += w3 * xv.z; acc[3].w += w3 * xv.w;
    }

#pragma unroll
    for (int a = 0; a < 4; a++) {
        float bb = __ldg(&bias[h0 + a]);
        float4 r = acc[a];
        r.x += bb; r.y += bb; r.z += bb; r.w += bb;
        *(float4*)&out[((b * 64 + h0 + a) * 512 + t) * 64 + f0] = r;
    }
}

// ---------------------------------------------------------------------------
// Kernel 2: banded correlation (r9 version: conflict-free fills, 4t x 4d).
// V[b,h,t,d] = (1/8) * sum_f Q[b,h,t,f] * K[b,h,t-31+d,f]
// grid = B*H*(T/64) = 1024 blocks, 128 threads.
// ---------------------------------------------------------------------------
__global__ void __launch_bounds__(128) k_corr() {
    const int tid = threadIdx.x;
    const int warp = tid >> 5, lane = tid & 31;
    const int t0 = (blockIdx.x & 7) * 64;
    const int h  = (blockIdx.x >> 3) & 63;
    const int b  = blockIdx.x >> 9;

    __shared__ float Qs[64][68];    // [f][i]
    __shared__ float Ks[64][100];   // [f][r], r = t_global-(t0-31), 0..94

    const float* qg = g_Q + ((b * 64 + h) * 512 + t0) * 64;
    const float* kg = g_K + ((b * 64 + h) * 512) * 64;

#pragma unroll
    for (int it = 0; it < 4; it++) {
        int fq = warp * 4 + it;
#pragma unroll
        for (int sub = 0; sub < 2; sub++) {
            int i = lane + sub * 32;
            float4 v = *(const float4*)&qg[i * 64 + fq * 4];
            Qs[4 * fq + 0][i] = v.x;
            Qs[4 * fq + 1][i] = v.y;
            Qs[4 * fq + 2][i] = v.z;
            Qs[4 * fq + 3][i] = v.w;
        }
    }
#pragma unroll
    for (int it = 0; it < 4; it++) {
        int fq = warp * 4 + it;
#pragma unroll
        for (int sub = 0; sub < 3; sub++) {
            int r = lane + sub * 32;
            if (r < 95) {
                int tr = t0 - 31 + r;
                float4 v = make_float4(0.f, 0.f, 0.f, 0.f);
                if (tr >= 0) v = *(const float4*)&kg[tr * 64 + fq * 4];
                Ks[4 * fq + 0][r] = v.x;
                Ks[4 * fq + 1][r] = v.y;
                Ks[4 * fq + 2][r] = v.z;
                Ks[4 * fq + 3][r] = v.w;
            }
        }
    }
    __syncthreads();

    const int d0 = (tid & 7) * 4;
    const int i0 = (tid >> 3) * 4;

    float acc[4][4];
#pragma unroll
    for (int a = 0; a < 4; a++)
#pragma unroll
        for (int e = 0; e < 4; e++) acc[a][e] = 0.f;

#pragma unroll 8
    for (int f = 0; f < 64; f++) {
        float4 q4 = *(const float4*)&Qs[f][i0];
        float4 k0 = *(const float4*)&Ks[f][i0 + d0];
        float4 k1 = *(const float4*)&Ks[f][i0 + d0 + 4];
        float qq[4] = {q4.x, q4.y, q4.z, q4.w};
        float kk[8] = {k0.x, k0.y, k0.z, k0.w, k1.x, k1.y, k1.z, k1.w};
#pragma unroll
        for (int a = 0; a < 4; a++)
#pragma unroll
            for (int e = 0; e < 4; e++)
                acc[a][e] += qq[a] * kk[a + e];
    }

    float* vg = g_V + ((b * 64 + h) * 512 + t0) * 32;
#pragma unroll
    for (int a = 0; a < 4; a++) {
        float4 r = make_float4(acc[a][0] * 0.125f, acc[a][1] * 0.125f,
                               acc[a][2] * 0.125f, acc[a][3] * 0.125f);
        *(float4*)&vg[(i0 + a) * 32 + d0] = r;
    }
}

// ---------------------------------------------------------------------------
// Kernel 3: (5,3) conv over (T,dmax) reducing H->1, + softmax over dmax.
// (conv bias dropped: uniform shift is softmax-invariant)
// grid = B*(T/8) = 128 blocks, 128 threads.
// ---------------------------------------------------------------------------
__global__ void __launch_bounds__(128) k_convsoftmax(const float* __restrict__ wconv) {
    const int tid = threadIdx.x;
    const int b  = blockIdx.x >> 6;
    const int t0 = (blockIdx.x & 63) * 8;

    __shared__ float Vs[16][12][34];
    __shared__ float wcs[64][16];
    __shared__ float red[8][33];

    for (int idx = tid; idx < 960; idx += 128)
        wcs[idx / 15][idx % 15] = wconv[idx];
    for (int idx = tid; idx < 16 * 12; idx += 128) {
        Vs[idx / 12][idx % 12][0]  = 0.0f;
        Vs[idx / 12][idx % 12][33] = 0.0f;
    }

    const int tl = tid >> 4;
    const int d  = (tid & 15) * 2;

    float accA0 = 0.f, accA1 = 0.f, accB0 = 0.f, accB1 = 0.f;

    for (int hc = 0; hc < 4; hc++) {
        __syncthreads();
        for (int g = tid; g < 1536; g += 128) {
            int dq = g & 7;
            int hr = g >> 3;
            int r  = hr % 12;
            int hl = hr / 12;
            int tt = t0 - 4 + r;
            float4 v = make_float4(0.f, 0.f, 0.f, 0.f);
            if (tt >= 0)
                v = *(const float4*)&g_V[((b * 64 + hc * 16 + hl) * 512 + tt) * 32 + dq * 4];
            Vs[hl][r][1 + dq * 4 + 0] = v.x;
            Vs[hl][r][1 + dq * 4 + 1] = v.y;
            Vs[hl][r][1 + dq * 4 + 2] = v.z;
            Vs[hl][r][1 + dq * 4 + 3] = v.w;
        }
        __syncthreads();

#pragma unroll 2
        for (int hl = 0; hl < 16; hl++) {
            int hh = hc * 16 + hl;
            float wreg[16];
#pragma unroll
            for (int k4 = 0; k4 < 4; k4++) {
                float4 wv = *(const float4*)&wcs[hh][k4 * 4];
                wreg[k4 * 4 + 0] = wv.x; wreg[k4 * 4 + 1] = wv.y;
                wreg[k4 * 4 + 2] = wv.z; wreg[k4 * 4 + 3] = wv.w;
            }
#pragma unroll
            for (int i = 0; i < 5; i++) {
                float2 u = *(const float2*)&Vs[hl][tl + i][d];
                float2 v = *(const float2*)&Vs[hl][tl + i][d + 2];
                float w0 = wreg[i * 3], w1 = wreg[i * 3 + 1], w2 = wreg[i * 3 + 2];
                if (i & 1) {
                    accB0 += u.x * w0 + u.y * w1 + v.x * w2;
                    accB1 += u.y * w0 + v.x * w1 + v.y * w2;
                } else {
                    accA0 += u.x * w0 + u.y * w1 + v.x * w2;
                    accA1 += u.y * w0 + v.x * w1 + v.y * w2;
                }
            }
        }
    }

    red[tl][d]     = accA0 + accB0;
    red[tl][d + 1] = accA1 + accB1;
    __syncthreads();

    const int wd = tid >> 5, lane = tid & 31;
#pragma unroll
    for (int rr = 0; rr < 2; rr++) {
        int row = wd * 2 + rr;
        float v = red[row][lane];
        float mx = v;
#pragma unroll
        for (int o = 16; o > 0; o >>= 1)
            mx = fmaxf(mx, __shfl_xor_sync(0xffffffffu, mx, o));
        float e = __expf(v - mx);
        float s = e;
#pragma unroll
        for (int o = 16; o > 0; o >>= 1)
            s += __shfl_xor_sync(0xffffffffu, s, o);
        g_A[(b * 512 + t0 + row) * 32 + lane] = e / s;
    }
}

// ---------------------------------------------------------------------------
// Kernel 4: aligned[b,c,t,f] = sum_d A[b,t,d] * x_ref[b,c,t-31+d,f]
// grid = B*C*(T/32) = 2048 blocks, 128 threads. Thread tile 4t x 4f.
// NO rolling window: 7 direct X LDS per step (0 MOVs) -> FMA-bound.
// ---------------------------------------------------------------------------
__global__ void __launch_bounds__(128) k_align(const float* __restrict__ xref,
                                               float* __restrict__ out) {
    const int tid = threadIdx.x;
    const int t0 = (blockIdx.x & 15) * 32;
    const int c  = (blockIdx.x >> 4) & 63;
    const int b  = blockIdx.x >> 10;

    __shared__ float As[32][36];    // [i][d]
    __shared__ float Xs[63][68];    // [r][f], r = t_global-(t0-31), 0..62

    const float* ag = g_A + (b * 512 + t0) * 32;
    const float* xg = xref + ((b * 64 + c) * 512) * 64;

    for (int idx = tid; idx < 32 * 8; idx += 128) {
        int i = idx >> 3, dq = idx & 7;
        *(float4*)&As[i][dq * 4] = *(const float4*)&ag[i * 32 + dq * 4];
    }
    for (int idx = tid; idx < 63 * 16; idx += 128) {
        int r = idx >> 4, fq = idx & 15;
        int tr = t0 - 31 + r;
        float4 v = make_float4(0.f, 0.f, 0.f, 0.f);
        if (tr >= 0) v = *(const float4*)&xg[tr * 64 + fq * 4];
        *(float4*)&Xs[r][fq * 4] = v;
    }
    __syncthreads();

    const int f0 = (tid & 15) * 4;
    const int i0 = (tid >> 4) * 4;

    float4 acc[4];
#pragma unroll
    for (int a = 0; a < 4; a++) acc[a] = make_float4(0.f, 0.f, 0.f, 0.f);

#pragma unroll
    for (int d0 = 0; d0 < 32; d0 += 4) {
        float4 av[4];
#pragma unroll
        for (int a = 0; a < 4; a++) av[a] = *(const float4*)&As[i0 + a][d0];
        float4 xv[7];
#pragma unroll
        for (int k = 0; k < 7; k++)
            xv[k] = *(const float4*)&Xs[i0 + d0 + k][f0];
#pragma unroll
        for (int a = 0; a < 4; a++) {
            float aa[4] = {av[a].x, av[a].y, av[a].z, av[a].w};
#pragma unroll
            for (int dd = 0; dd < 4; dd++) {
                float4 x4 = xv[a + dd];
                acc[a].x += aa[dd] * x4.x;
                acc[a].y += aa[dd] * x4.y;
                acc[a].z += aa[dd] * x4.z;
                acc[a].w += aa[dd] * x4.w;
            }
        }
    }

    float* og = out + ((b * 64 + c) * 512 + t0) * 64;
#pragma unroll
    for (int a = 0; a < 4; a++)
        *(float4*)&og[(i0 + a) * 64 + f0] = acc[a];
}

// ---------------------------------------------------------------------------
extern "C" void kernel_launch(void* const* d_in, const int* in_sizes, int n_in,
                              void* d_out, int out_size) {
    (void)in_sizes; (void)n_in; (void)out_size;
    const float* x_mic  = (const float*)d_in[0];
    const float* x_ref  = (const float*)d_in[1];
    const float* w_mic  = (const float*)d_in[2];
    const float* b_mic  = (const float*)d_in[3];
    const float* w_ref  = (const float*)d_in[4];
    const float* b_ref  = (const float*)d_in[5];
    const float* w_conv = (const float*)d_in[6];
    float* out = (float*)d_out;

    k_chanmix<<<2 * Bn * Tn, 256>>>(x_mic, w_mic, b_mic, x_ref, w_ref, b_ref);
    k_corr<<<Bn * Hn * (Tn / 64), 128>>>();
    k_convsoftmax<<<Bn * (Tn / 8), 128>>>(w_conv);
    k_align<<<Bn * Cn * (Tn / 32), 128>>>(x_ref, out);
}

// round 11
// speedup vs baseline: 1.2100x; 1.0349x over previous
#include <cuda_runtime.h>

// AlignBlock on sm_103a, round 11: r10 winner (81.7us) + gmem-direct align.
//  - chanmix: natural-layout weights (r10, at scalar-FMA floor ~31us)
//  - corr: conflict-free fills + 4t x 4d (r9/r10, ~11.5us)
//  - conv+softmax: unchanged (~3.5us)
//  - align: X read directly from gmem (L1/L2-resident, coalesced) instead of
//    smem -> removes the 7 B/FMA crossbar bottleneck + fill phase.
// Shapes: B=2, C=H=64, T=512, F=64, DMAX=32. All fp32.

#define Bn 2
#define Cn 64
#define Hn 64
#define Tn 512
#define Fn 64
#define Dn 32

__device__ float g_Q[Bn * Hn * Tn * Fn];
__device__ float g_K[Bn * Hn * Tn * Fn];
__device__ float g_V[Bn * Hn * Tn * Dn];
__device__ float g_A[Bn * Tn * Dn];

// ---------------------------------------------------------------------------
// Kernel 1: channel mix for Q AND K (merged). (r10 version)
// out[b,h,t,f] = sum_c w[h,c] * x[b,c,t,f] + bias[h]
// grid = 2*B*T = 2048 blocks, 256 threads. Thread tile 4h x 4f.
// ---------------------------------------------------------------------------
__global__ void __launch_bounds__(256) k_chanmix(const float* __restrict__ xm,
                                                 const float* __restrict__ wm,
                                                 const float* __restrict__ bm,
                                                 const float* __restrict__ xr,
                                                 const float* __restrict__ wr,
                                                 const float* __restrict__ br) {
    const int tid = threadIdx.x;
    const int which = blockIdx.x >> 10;
    const int rem = blockIdx.x & 1023;
    const int b = rem >> 9;
    const int t = rem & 511;

    const float* x    = which ? xr : xm;
    const float* w    = which ? wr : wm;
    const float* bias = which ? br : bm;
    float* out        = which ? g_K : g_Q;

    __shared__ float xs[64][68];        // [c][f]
    __shared__ float ws[64][68];        // [h][c]  (natural)

#pragma unroll
    for (int it = 0; it < 4; it++) {
        int idx = tid + it * 256;               // 0..1023
        int q4 = (idx & 15) * 4;
        int r  = idx >> 4;
        *(float4*)&xs[r][q4] =
            *(const float4*)&x[((b * 64 + r) * 512 + t) * 64 + q4];
        *(float4*)&ws[r][q4] = *(const float4*)&w[r * 64 + q4];
    }
    __syncthreads();

    const int f0 = (tid & 15) * 4;
    const int h0 = (tid >> 4) * 4;

    float4 acc[4];
#pragma unroll
    for (int a = 0; a < 4; a++) acc[a] = make_float4(0.f, 0.f, 0.f, 0.f);

#pragma unroll 8
    for (int c = 0; c < 64; c++) {
        float4 xv = *(const float4*)&xs[c][f0];
        float w0 = ws[h0 + 0][c];
        float w1 = ws[h0 + 1][c];
        float w2 = ws[h0 + 2][c];
        float w3 = ws[h0 + 3][c];
        acc[0].x += w0 * xv.x; acc[0].y += w0 * xv.y;
        acc[0].z += w0 * xv.z; acc[0].w += w0 * xv.w;
        acc[1].x += w1 * xv.x; acc[1].y += w1 * xv.y;
        acc[1].z += w1 * xv.z; acc[1].w += w1 * xv.w;
        acc[2].x += w2 * xv.x; acc[2].y += w2 * xv.y;
        acc[2].z += w2 * xv.z; acc[2].w += w2 * xv.w;
        acc[3].x += w3 * xv.x; acc[3].y += w3 * xv.y;
        acc[3].z += w3 * xv.z; acc[3].w += w3 * xv.w;
    }

#pragma unroll
    for (int a = 0; a < 4; a++) {
        float bb = __ldg(&bias[h0 + a]);
        float4 r = acc[a];
        r.x += bb; r.y += bb; r.z += bb; r.w += bb;
        *(float4*)&out[((b * 64 + h0 + a) * 512 + t) * 64 + f0] = r;
    }
}

// ---------------------------------------------------------------------------
// Kernel 2: banded correlation (r9/r10 version).
// V[b,h,t,d] = (1/8) * sum_f Q[b,h,t,f] * K[b,h,t-31+d,f]
// grid = B*H*(T/64) = 1024 blocks, 128 threads.
// ---------------------------------------------------------------------------
__global__ void __launch_bounds__(128) k_corr() {
    const int tid = threadIdx.x;
    const int warp = tid >> 5, lane = tid & 31;
    const int t0 = (blockIdx.x & 7) * 64;
    const int h  = (blockIdx.x >> 3) & 63;
    const int b  = blockIdx.x >> 9;

    __shared__ float Qs[64][68];    // [f][i]
    __shared__ float Ks[64][100];   // [f][r], r = t_global-(t0-31), 0..94

    const float* qg = g_Q + ((b * 64 + h) * 512 + t0) * 64;
    const float* kg = g_K + ((b * 64 + h) * 512) * 64;

#pragma unroll
    for (int it = 0; it < 4; it++) {
        int fq = warp * 4 + it;
#pragma unroll
        for (int sub = 0; sub < 2; sub++) {
            int i = lane + sub * 32;
            float4 v = *(const float4*)&qg[i * 64 + fq * 4];
            Qs[4 * fq + 0][i] = v.x;
            Qs[4 * fq + 1][i] = v.y;
            Qs[4 * fq + 2][i] = v.z;
            Qs[4 * fq + 3][i] = v.w;
        }
    }
#pragma unroll
    for (int it = 0; it < 4; it++) {
        int fq = warp * 4 + it;
#pragma unroll
        for (int sub = 0; sub < 3; sub++) {
            int r = lane + sub * 32;
            if (r < 95) {
                int tr = t0 - 31 + r;
                float4 v = make_float4(0.f, 0.f, 0.f, 0.f);
                if (tr >= 0) v = *(const float4*)&kg[tr * 64 + fq * 4];
                Ks[4 * fq + 0][r] = v.x;
                Ks[4 * fq + 1][r] = v.y;
                Ks[4 * fq + 2][r] = v.z;
                Ks[4 * fq + 3][r] = v.w;
            }
        }
    }
    __syncthreads();

    const int d0 = (tid & 7) * 4;
    const int i0 = (tid >> 3) * 4;

    float acc[4][4];
#pragma unroll
    for (int a = 0; a < 4; a++)
#pragma unroll
        for (int e = 0; e < 4; e++) acc[a][e] = 0.f;

#pragma unroll 8
    for (int f = 0; f < 64; f++) {
        float4 q4 = *(const float4*)&Qs[f][i0];
        float4 k0 = *(const float4*)&Ks[f][i0 + d0];
        float4 k1 = *(const float4*)&Ks[f][i0 + d0 + 4];
        float qq[4] = {q4.x, q4.y, q4.z, q4.w};
        float kk[8] = {k0.x, k0.y, k0.z, k0.w, k1.x, k1.y, k1.z, k1.w};
#pragma unroll
        for (int a = 0; a < 4; a++)
#pragma unroll
            for (int e = 0; e < 4; e++)
                acc[a][e] += qq[a] * kk[a + e];
    }

    float* vg = g_V + ((b * 64 + h) * 512 + t0) * 32;
#pragma unroll
    for (int a = 0; a < 4; a++) {
        float4 r = make_float4(acc[a][0] * 0.125f, acc[a][1] * 0.125f,
                               acc[a][2] * 0.125f, acc[a][3] * 0.125f);
        *(float4*)&vg[(i0 + a) * 32 + d0] = r;
    }
}

// ---------------------------------------------------------------------------
// Kernel 3: (5,3) conv over (T,dmax) reducing H->1, + softmax over dmax.
// (conv bias dropped: uniform shift is softmax-invariant)
// grid = B*(T/8) = 128 blocks, 128 threads.
// ---------------------------------------------------------------------------
__global__ void __launch_bounds__(128) k_convsoftmax(const float* __restrict__ wconv) {
    const int tid = threadIdx.x;
    const int b  = blockIdx.x >> 6;
    const int t0 = (blockIdx.x & 63) * 8;

    __shared__ float Vs[16][12][34];
    __shared__ float wcs[64][16];
    __shared__ float red[8][33];

    for (int idx = tid; idx < 960; idx += 128)
        wcs[idx / 15][idx % 15] = wconv[idx];
    for (int idx = tid; idx < 16 * 12; idx += 128) {
        Vs[idx / 12][idx % 12][0]  = 0.0f;
        Vs[idx / 12][idx % 12][33] = 0.0f;
    }

    const int tl = tid >> 4;
    const int d  = (tid & 15) * 2;

    float accA0 = 0.f, accA1 = 0.f, accB0 = 0.f, accB1 = 0.f;

    for (int hc = 0; hc < 4; hc++) {
        __syncthreads();
        for (int g = tid; g < 1536; g += 128) {
            int dq = g & 7;
            int hr = g >> 3;
            int r  = hr % 12;
            int hl = hr / 12;
            int tt = t0 - 4 + r;
            float4 v = make_float4(0.f, 0.f, 0.f, 0.f);
            if (tt >= 0)
                v = *(const float4*)&g_V[((b * 64 + hc * 16 + hl) * 512 + tt) * 32 + dq * 4];
            Vs[hl][r][1 + dq * 4 + 0] = v.x;
            Vs[hl][r][1 + dq * 4 + 1] = v.y;
            Vs[hl][r][1 + dq * 4 + 2] = v.z;
            Vs[hl][r][1 + dq * 4 + 3] = v.w;
        }
        __syncthreads();

#pragma unroll 2
        for (int hl = 0; hl < 16; hl++) {
            int hh = hc * 16 + hl;
            float wreg[16];
#pragma unroll
            for (int k4 = 0; k4 < 4; k4++) {
                float4 wv = *(const float4*)&wcs[hh][k4 * 4];
                wreg[k4 * 4 + 0] = wv.x; wreg[k4 * 4 + 1] = wv.y;
                wreg[k4 * 4 + 2] = wv.z; wreg[k4 * 4 + 3] = wv.w;
            }
#pragma unroll
            for (int i = 0; i < 5; i++) {
                float2 u = *(const float2*)&Vs[hl][tl + i][d];
                float2 v = *(const float2*)&Vs[hl][tl + i][d + 2];
                float w0 = wreg[i * 3], w1 = wreg[i * 3 + 1], w2 = wreg[i * 3 + 2];
                if (i & 1) {
                    accB0 += u.x * w0 + u.y * w1 + v.x * w2;
                    accB1 += u.y * w0 + v.x * w1 + v.y * w2;
                } else {
                    accA0 += u.x * w0 + u.y * w1 + v.x * w2;
                    accA1 += u.y * w0 + v.x * w1 + v.y * w2;
                }
            }
        }
    }

    red[tl][d]     = accA0 + accB0;
    red[tl][d + 1] = accA1 + accB1;
    __syncthreads();

    const int wd = tid >> 5, lane = tid & 31;
#pragma unroll
    for (int rr = 0; rr < 2; rr++) {
        int row = wd * 2 + rr;
        float v = red[row][lane];
        float mx = v;
#pragma unroll
        for (int o = 16; o > 0; o >>= 1)
            mx = fmaxf(mx, __shfl_xor_sync(0xffffffffu, mx, o));
        float e = __expf(v - mx);
        float s = e;
#pragma unroll
        for (int o = 16; o > 0; o >>= 1)
            s += __shfl_xor_sync(0xffffffffu, s, o);
        g_A[(b * 512 + t0 + row) * 32 + lane] = e / s;
    }
}

// ---------------------------------------------------------------------------
// Kernel 4: aligned[b,c,t,f] = sum_d A[b,t,d] * x_ref[b,c,t-31+d,f]
// grid = B*C*(T/32) = 2048 blocks, 128 threads. Thread tile 4t x 4f.
// X read DIRECTLY from gmem (coalesced 2x256B per warp-LDG; block working set
// 16KB = L1-resident; xref L2-resident). A stays in smem (broadcast reads).
// Boundary tile (t0==0) takes a separate predicated path.
// ---------------------------------------------------------------------------
__device__ __forceinline__ void align_body(const float* __restrict__ xg,
                                           const float (*As)[36],
                                           float4* acc, int i0, int tbase,
                                           bool guard) {
#pragma unroll
    for (int d0 = 0; d0 < 32; d0 += 4) {
        float4 av[4];
#pragma unroll
        for (int a = 0; a < 4; a++) av[a] = *(const float4*)&As[i0 + a][d0];
        float4 xv[7];
#pragma unroll
        for (int k = 0; k < 7; k++) {
            int tg = tbase + d0 + k;
            if (guard)
                xv[k] = (tg >= 0) ? *(const float4*)&xg[tg * 64]
                                  : make_float4(0.f, 0.f, 0.f, 0.f);
            else
                xv[k] = *(const float4*)&xg[tg * 64];
        }
#pragma unroll
        for (int a = 0; a < 4; a++) {
            float aa[4] = {av[a].x, av[a].y, av[a].z, av[a].w};
#pragma unroll
            for (int dd = 0; dd < 4; dd++) {
                float4 x4 = xv[a + dd];
                acc[a].x += aa[dd] * x4.x;
                acc[a].y += aa[dd] * x4.y;
                acc[a].z += aa[dd] * x4.z;
                acc[a].w += aa[dd] * x4.w;
            }
        }
    }
}

__global__ void __launch_bounds__(128) k_align(const float* __restrict__ xref,
                                               float* __restrict__ out) {
    const int tid = threadIdx.x;
    const int t0 = (blockIdx.x & 15) * 32;
    const int c  = (blockIdx.x >> 4) & 63;
    const int b  = blockIdx.x >> 10;

    __shared__ float As[32][36];    // [i][d]

    const float* ag = g_A + (b * 512 + t0) * 32;
#pragma unroll
    for (int it = 0; it < 2; it++) {
        int idx = tid + it * 128;               // 0..255 quads
        int i = idx >> 3, dq = idx & 7;
        *(float4*)&As[i][dq * 4] = *(const float4*)&ag[i * 32 + dq * 4];
    }
    __syncthreads();

    const int f0 = (tid & 15) * 4;
    const int i0 = (tid >> 4) * 4;
    const int tbase = t0 + i0 - 31;             // global t at (d0=0, k=0)

    const float* xg = xref + ((b * 64 + c) * 512) * 64 + f0;

    float4 acc[4];
#pragma unroll
    for (int a = 0; a < 4; a++) acc[a] = make_float4(0.f, 0.f, 0.f, 0.f);

    if (t0 == 0)
        align_body(xg, As, acc, i0, tbase, true);
    else
        align_body(xg, As, acc, i0, tbase, false);

    float* og = out + ((b * 64 + c) * 512 + t0) * 64;
#pragma unroll
    for (int a = 0; a < 4; a++)
        *(float4*)&og[(i0 + a) * 64 + f0] = acc[a];
}

// ---------------------------------------------------------------------------
extern "C" void kernel_launch(void* const* d_in, const int* in_sizes, int n_in,
                              void* d_out, int out_size) {
    (void)in_sizes; (void)n_in; (void)out_size;
    const float* x_mic  = (const float*)d_in[0];
    const float* x_ref  = (const float*)d_in[1];
    const float* w_mic  = (const float*)d_in[2];
    const float* b_mic  = (const float*)d_in[3];
    const float* w_ref  = (const float*)d_in[4];
    const float* b_ref  = (const float*)d_in[5];
    const float* w_conv = (const float*)d_in[6];
    float* out = (float*)d_out;

    k_chanmix<<<2 * Bn * Tn, 256>>>(x_mic, w_mic, b_mic, x_ref, w_ref, b_ref);
    k_corr<<<Bn * Hn * (Tn / 64), 128>>>();
    k_convsoftmax<<<Bn * (Tn / 8), 128>>>(w_conv);
    k_align<<<Bn * Cn * (Tn / 32), 128>>>(x_ref, out);
}